// round 3
// baseline (speedup 1.0000x reference)
#include <cuda_runtime.h>
#include <math_constants.h>
#include <cstdint>

#define NROWS 2048
#define DIN   256
#define DPROJ 256   // Q[0:64) K[64:128) V[128:192) R[192:256)
#define DK    64
#define DR    64
#define DV    64

#define TILE_KEYS  64
#define NTILES     (NROWS / TILE_KEYS)     // 32
#define STAGES     2
#define TILE_FLOATS (TILE_KEYS * DR)       // 4096
#define TILE_BYTES  (TILE_FLOATS * 4)      // 16384

// Scratch for the projection (2048 x 256 fp32 = 2 MB). Device global => allowed.
__device__ float g_proj[NROWS * DPROJ];

__device__ __forceinline__ uint32_t smem_u32(const void* p) {
    return (uint32_t)__cvta_generic_to_shared(p);
}

__device__ __forceinline__ void mbar_wait(uint32_t mbar, int parity) {
    asm volatile(
        "{\n\t"
        ".reg .pred P;\n\t"
        "WAIT_%=:\n\t"
        "mbarrier.try_wait.parity.acquire.cta.shared::cta.b64 P, [%0], %1, 0x989680;\n\t"
        "@P bra.uni DONE_%=;\n\t"
        "bra.uni WAIT_%=;\n\t"
        "DONE_%=:\n\t"
        "}"
        :: "r"(mbar), "r"(parity) : "memory");
}

// ---------------------------------------------------------------------------
// Kernel 1: proj = H @ W^T   (2048x256) = (2048x256) @ (256x256)^T
// 64x64x32 smem-tiled fp32 GEMM, 4x4 register micro-tile, 256 threads.
// ---------------------------------------------------------------------------
__global__ __launch_bounds__(256) void proj_gemm_kernel(
    const float* __restrict__ H, const float* __restrict__ W)
{
    const int BM = 64, BN = 64, BK = 32;
    __shared__ float As[BM][BK + 1];
    __shared__ float Bs[BN][BK + 1];

    const int tx = threadIdx.x & 15;
    const int ty = threadIdx.x >> 4;
    const int bm = blockIdx.y * BM;
    const int bn = blockIdx.x * BN;

    float acc[4][4];
#pragma unroll
    for (int a = 0; a < 4; a++)
#pragma unroll
        for (int b = 0; b < 4; b++) acc[a][b] = 0.f;

    const int t   = threadIdx.x;
    const int row = t >> 2;
    const int cg  = (t & 3) * 8;

    for (int k0 = 0; k0 < DIN; k0 += BK) {
#pragma unroll
        for (int h = 0; h < 2; h++) {
            float4 a4 = *(const float4*)&H[(size_t)(bm + row) * DIN + k0 + cg + 4 * h];
            As[row][cg + 4 * h + 0] = a4.x; As[row][cg + 4 * h + 1] = a4.y;
            As[row][cg + 4 * h + 2] = a4.z; As[row][cg + 4 * h + 3] = a4.w;
            float4 b4 = *(const float4*)&W[(size_t)(bn + row) * DIN + k0 + cg + 4 * h];
            Bs[row][cg + 4 * h + 0] = b4.x; Bs[row][cg + 4 * h + 1] = b4.y;
            Bs[row][cg + 4 * h + 2] = b4.z; Bs[row][cg + 4 * h + 3] = b4.w;
        }
        __syncthreads();

#pragma unroll
        for (int k = 0; k < BK; k++) {
            float af[4], bf[4];
#pragma unroll
            for (int a = 0; a < 4; a++) af[a] = As[ty * 4 + a][k];
#pragma unroll
            for (int b = 0; b < 4; b++) bf[b] = Bs[tx * 4 + b][k];
#pragma unroll
            for (int a = 0; a < 4; a++)
#pragma unroll
                for (int b = 0; b < 4; b++) acc[a][b] = fmaf(af[a], bf[b], acc[a][b]);
        }
        __syncthreads();
    }

#pragma unroll
    for (int a = 0; a < 4; a++)
#pragma unroll
        for (int b = 0; b < 4; b++)
            g_proj[(size_t)(bm + ty * 4 + a) * DPROJ + bn + tx * 4 + b] = acc[a][b];
}

// ---------------------------------------------------------------------------
// Kernel 2: fused attention row kernel with TMA-bulk D pipeline.
// One CTA per row i, 9 warps:
//   warp 8  = producer: cp.async.bulk 16KB D-tiles (64 keys) into a 2-stage
//             smem ring with mbarrier expect_tx completion.
//   warps 0-7 = consumers: per tile, warp w handles keys [w*8, w*8+8) using
//             the 16-lane-group layout (h = lane>>4 owns alternating keys,
//             lane&15 owns 4 dims -> LDS.128 from the ring, LDG.128 K/V from
//             L2-resident proj, 4-level shfl dot, online softmax).
// Final combine over 16 group-partials through smem.
// ---------------------------------------------------------------------------
__global__ __launch_bounds__(288) void attn_fused_kernel(
    const float* __restrict__ D, float* __restrict__ out)
{
    __shared__ float d_tiles[STAGES][TILE_FLOATS];
    __shared__ __align__(8) unsigned long long mbar_full[STAGES];
    __shared__ __align__(8) unsigned long long mbar_empty[STAGES];
    __shared__ float sm_m[16];
    __shared__ float sm_l[16];
    __shared__ float sm_acc[16][DV];

    const int i    = blockIdx.x;
    const int tid  = threadIdx.x;
    const int warp = tid >> 5;
    const int lane = tid & 31;

    if (tid == 0) {
#pragma unroll
        for (int s = 0; s < STAGES; s++) {
            asm volatile("mbarrier.init.shared.b64 [%0], %1;"
                         :: "r"(smem_u32(&mbar_full[s])), "r"(1) : "memory");
            asm volatile("mbarrier.init.shared.b64 [%0], %1;"
                         :: "r"(smem_u32(&mbar_empty[s])), "r"(8) : "memory");
        }
    }
    __syncthreads();

    if (warp == 8) {
        // -------- producer --------
        if (lane == 0) {
            const char* src = (const char*)(D + (size_t)i * NROWS * DR);
            int st = 0, ph = 1;   // fresh barrier: parity-1 wait passes immediately
#pragma unroll 1
            for (int t = 0; t < NTILES; t++) {
                mbar_wait(smem_u32(&mbar_empty[st]), ph);
                const uint32_t fb = smem_u32(&mbar_full[st]);
                asm volatile("mbarrier.arrive.expect_tx.shared.b64 _, [%0], %1;"
                             :: "r"(fb), "r"(TILE_BYTES) : "memory");
                asm volatile(
                    "cp.async.bulk.shared::cta.global.mbarrier::complete_tx::bytes "
                    "[%0], [%1], %2, [%3];"
                    :: "r"(smem_u32(&d_tiles[st][0])),
                       "l"(src + (size_t)t * TILE_BYTES),
                       "r"(TILE_BYTES), "r"(fb) : "memory");
                if (++st == STAGES) { st = 0; ph ^= 1; }
            }
        }
    } else {
        // -------- consumer --------
        const int h  = lane >> 4;       // group within warp
        const int lx = lane & 15;       // lane within group -> dims 4*lx..4*lx+3
        const float scale = 0.08838834764831845f;   // 1/sqrt(128)

        const float4 q4 = *(const float4*)&g_proj[(size_t)i * DPROJ + 4 * lx];
        const float4 r4 = *(const float4*)&g_proj[(size_t)i * DPROJ + 192 + 4 * lx];

        float  m = -CUDART_INF_F;
        float  l = 0.f;
        float4 acc = make_float4(0.f, 0.f, 0.f, 0.f);

        const int kb = warp * 8;        // this warp's keys within each tile
        int st = 0, ph = 0;

#pragma unroll 1
        for (int t = 0; t < NTILES; t++) {
            mbar_wait(smem_u32(&mbar_full[st]), ph);
            const float* Dt = d_tiles[st];
            const int jt0 = t * TILE_KEYS + kb;

#pragma unroll
            for (int it = 0; it < 2; it++) {
                float4 d4[2], k4[2], v4[2];
                float  s[2];
#pragma unroll
                for (int u = 0; u < 2; u++) {
                    const int kk = kb + it * 4 + 2 * u + h;   // in-tile key
                    const int j  = jt0 + it * 4 + 2 * u + h;  // global key
                    d4[u] = *(const float4*)&Dt[kk * DR + 4 * lx];
                    k4[u] = *(const float4*)&g_proj[(size_t)j * DPROJ + 64 + 4 * lx];
                    v4[u] = *(const float4*)&g_proj[(size_t)j * DPROJ + 128 + 4 * lx];
                }
#pragma unroll
                for (int u = 0; u < 2; u++) {
                    float t0 = d4[u].x * r4.x;
                    t0 = fmaf(d4[u].y, r4.y, t0);
                    t0 = fmaf(d4[u].z, r4.z, t0);
                    t0 = fmaf(d4[u].w, r4.w, t0);
                    t0 = fmaf(k4[u].x, q4.x, t0);
                    t0 = fmaf(k4[u].y, q4.y, t0);
                    t0 = fmaf(k4[u].z, q4.z, t0);
                    t0 = fmaf(k4[u].w, q4.w, t0);
                    s[u] = t0;
                }
                // 4-level butterfly within each 16-lane group
#pragma unroll
                for (int o = 1; o < 16; o <<= 1) {
                    s[0] += __shfl_xor_sync(0xffffffffu, s[0], o);
                    s[1] += __shfl_xor_sync(0xffffffffu, s[1], o);
                }
                s[0] *= scale;
                s[1] *= scale;

                const float mnew = fmaxf(m, fmaxf(s[0], s[1]));
                const float c  = __expf(m - mnew);
                const float w0 = __expf(s[0] - mnew);
                const float w1 = __expf(s[1] - mnew);

                l = fmaf(l, c, w0 + w1);
                acc.x = fmaf(w1, v4[1].x, fmaf(w0, v4[0].x, acc.x * c));
                acc.y = fmaf(w1, v4[1].y, fmaf(w0, v4[0].y, acc.y * c));
                acc.z = fmaf(w1, v4[1].z, fmaf(w0, v4[0].z, acc.z * c));
                acc.w = fmaf(w1, v4[1].w, fmaf(w0, v4[0].w, acc.w * c));
                m = mnew;
            }

            if (lane == 0)
                asm volatile("mbarrier.arrive.shared.b64 _, [%0];"
                             :: "r"(smem_u32(&mbar_empty[st])) : "memory");
            if (++st == STAGES) { st = 0; ph ^= 1; }
        }

        const int g = warp * 2 + h;
        if (lx == 0) { sm_m[g] = m; sm_l[g] = l; }
        *(float4*)&sm_acc[g][4 * lx] = acc;
    }

    __syncthreads();

    if (tid < DV) {
        const int d = tid;
        float M = sm_m[0];
#pragma unroll
        for (int w = 1; w < 16; w++) M = fmaxf(M, sm_m[w]);
        float L = 0.f, o = 0.f;
#pragma unroll
        for (int w = 0; w < 16; w++) {
            const float cc = __expf(sm_m[w] - M);
            L = fmaf(sm_l[w], cc, L);
            o = fmaf(sm_acc[w][d], cc, o);
        }
        out[(size_t)i * DV + d] = o / L;
    }
}

// ---------------------------------------------------------------------------
extern "C" void kernel_launch(void* const* d_in, const int* in_sizes, int n_in,
                              void* d_out, int out_size)
{
    const float* H = (const float*)d_in[0];   // (2048, 256)
    const float* D = (const float*)d_in[1];   // (2048, 2048, 64)
    const float* W = (const float*)d_in[2];   // (256, 256)
    float* out = (float*)d_out;               // (2048, 64)

    dim3 g1(DPROJ / 64, NROWS / 64);          // (4, 32)
    proj_gemm_kernel<<<g1, 256>>>(H, W);
    attn_fused_kernel<<<NROWS, 288>>>(D, out);
}

// round 4
// speedup vs baseline: 1.4125x; 1.4125x over previous
#include <cuda_runtime.h>
#include <math_constants.h>
#include <cstdint>

#define NROWS 2048
#define DIN   256
#define DPROJ 256   // Q[0:64) K[64:128) V[128:192) R[192:256)
#define DK    64
#define DR    64
#define DV    64

#define G_ROWS     4            // rows per CTA
#define TILE_KEYS  64           // keys per smem K/V tile
#define HALF_KEYS  1024         // keys per CTA (row split in 2)
#define NT         (HALF_KEYS / TILE_KEYS)   // 16 tiles
#define NCTA_X     (NROWS / G_ROWS)          // 512
// dynamic smem: Ks[2][64][64] + Vs[2][64][64] + cm[16] + cl[16] + ca[4][4][64]
#define SMEM_FLOATS (2*TILE_KEYS*DK + 2*TILE_KEYS*DV + 16 + 16 + G_ROWS*4*DV)
#define SMEM_BYTES  (SMEM_FLOATS * 4)

// Scratch
__device__ float g_proj[NROWS * DPROJ];          // projection (2 MB)
__device__ float g_ml[2][NROWS][2];              // per-half (M, L)
__device__ float g_pa[2][NROWS][DV];             // per-half unnormalized acc

__device__ __forceinline__ uint32_t smem_u32(const void* p) {
    return (uint32_t)__cvta_generic_to_shared(p);
}
__device__ __forceinline__ void cp16(uint32_t dst, const void* src) {
    asm volatile("cp.async.cg.shared.global [%0], [%1], 16;"
                 :: "r"(dst), "l"(src) : "memory");
}

// ---------------------------------------------------------------------------
// Kernel 1: proj = H @ W^T
// ---------------------------------------------------------------------------
__global__ __launch_bounds__(256) void proj_gemm_kernel(
    const float* __restrict__ H, const float* __restrict__ W)
{
    const int BM = 64, BN = 64, BK = 32;
    __shared__ float As[BM][BK + 1];
    __shared__ float Bs[BN][BK + 1];

    const int tx = threadIdx.x & 15;
    const int ty = threadIdx.x >> 4;
    const int bm = blockIdx.y * BM;
    const int bn = blockIdx.x * BN;

    float acc[4][4];
#pragma unroll
    for (int a = 0; a < 4; a++)
#pragma unroll
        for (int b = 0; b < 4; b++) acc[a][b] = 0.f;

    const int t   = threadIdx.x;
    const int row = t >> 2;
    const int cg  = (t & 3) * 8;

    for (int k0 = 0; k0 < DIN; k0 += BK) {
#pragma unroll
        for (int h = 0; h < 2; h++) {
            float4 a4 = *(const float4*)&H[(size_t)(bm + row) * DIN + k0 + cg + 4 * h];
            As[row][cg + 4 * h + 0] = a4.x; As[row][cg + 4 * h + 1] = a4.y;
            As[row][cg + 4 * h + 2] = a4.z; As[row][cg + 4 * h + 3] = a4.w;
            float4 b4 = *(const float4*)&W[(size_t)(bn + row) * DIN + k0 + cg + 4 * h];
            Bs[row][cg + 4 * h + 0] = b4.x; Bs[row][cg + 4 * h + 1] = b4.y;
            Bs[row][cg + 4 * h + 2] = b4.z; Bs[row][cg + 4 * h + 3] = b4.w;
        }
        __syncthreads();
#pragma unroll
        for (int k = 0; k < BK; k++) {
            float af[4], bf[4];
#pragma unroll
            for (int a = 0; a < 4; a++) af[a] = As[ty * 4 + a][k];
#pragma unroll
            for (int b = 0; b < 4; b++) bf[b] = Bs[tx * 4 + b][k];
#pragma unroll
            for (int a = 0; a < 4; a++)
#pragma unroll
                for (int b = 0; b < 4; b++) acc[a][b] = fmaf(af[a], bf[b], acc[a][b]);
        }
        __syncthreads();
    }
#pragma unroll
    for (int a = 0; a < 4; a++)
#pragma unroll
        for (int b = 0; b < 4; b++)
            g_proj[(size_t)(bm + ty * 4 + a) * DPROJ + bn + tx * 4 + b] = acc[a][b];
}

// ---------------------------------------------------------------------------
// Kernel 2: partial fused attention.
// Grid (512, 2): blockIdx.x -> row group (4 rows), blockIdx.y = key half.
// 8 warps: warp w -> row_local = w>>1, key-subset h2 = w&1.
// K/V staged through double-buffered smem tiles (cp.async.cg), shared by the
// 4 rows -> K/V L2 traffic cut 4x. D is a straight LDG.128 DRAM stream.
// Per row-half: online softmax partial (M, L, acc) -> global scratch.
// ---------------------------------------------------------------------------
__global__ void __launch_bounds__(256, 3) attn_partial_kernel(
    const float* __restrict__ D)
{
    extern __shared__ float smem[];
    float* Ks = smem;                       // [2][TILE_KEYS][DK]
    float* Vs = Ks + 2 * TILE_KEYS * DK;    // [2][TILE_KEYS][DV]
    float* cm = Vs + 2 * TILE_KEYS * DV;    // [G_ROWS][4]
    float* cl = cm + 16;                    // [G_ROWS][4]
    float* ca = cl + 16;                    // [G_ROWS][4][DV]

    const int tid  = threadIdx.x;
    const int warp = tid >> 5;
    const int lane = tid & 31;
    const int h    = lane >> 4;          // group in warp
    const int lx   = lane & 15;          // lane in group -> dims 4*lx..+4
    const int rloc = warp >> 1;          // row within CTA
    const int h2   = warp & 1;           // key subset within tile
    const int q    = blockIdx.y;         // key half
    const int i    = blockIdx.x * G_ROWS + rloc;
    const int jq   = q * HALF_KEYS;

    const float scale = 0.08838834764831845f;  // 1/sqrt(128)
    float4 q4 = *(const float4*)&g_proj[(size_t)i * DPROJ + 4 * lx];
    float4 r4 = *(const float4*)&g_proj[(size_t)i * DPROJ + 192 + 4 * lx];
    q4.x *= scale; q4.y *= scale; q4.z *= scale; q4.w *= scale;
    r4.x *= scale; r4.y *= scale; r4.z *= scale; r4.w *= scale;

    const float* Drow = D + (size_t)i * NROWS * DR;

    // ---- prefetch tile 0 ----
    {
        const int jt = jq;   // tile 0 base
#pragma unroll
        for (int r = 0; r < 4; r++) {
            const int c   = tid + r * 256;      // 0..1023
            const int key = c >> 4;
            const int off = c & 15;             // 16B units
            const float* src = &g_proj[(size_t)(jt + key) * DPROJ + off * 4];
            cp16(smem_u32(&Ks[key * DK + off * 4]), src + DK);        // K
            cp16(smem_u32(&Vs[key * DV + off * 4]), src + 2 * DK);    // V
        }
        asm volatile("cp.async.commit_group;" ::: "memory");
    }

    float  m = -CUDART_INF_F;
    float  l = 0.f;
    float4 acc = make_float4(0.f, 0.f, 0.f, 0.f);

#pragma unroll 1
    for (int t = 0; t < NT; t++) {
        const int st = t & 1;
        if (t + 1 < NT) {
            const int jt = jq + (t + 1) * TILE_KEYS;
            const int sn = (t + 1) & 1;
#pragma unroll
            for (int r = 0; r < 4; r++) {
                const int c   = tid + r * 256;
                const int key = c >> 4;
                const int off = c & 15;
                const float* src = &g_proj[(size_t)(jt + key) * DPROJ + off * 4];
                cp16(smem_u32(&Ks[sn * TILE_KEYS * DK + key * DK + off * 4]), src + DK);
                cp16(smem_u32(&Vs[sn * TILE_KEYS * DV + key * DV + off * 4]), src + 2 * DK);
            }
            asm volatile("cp.async.commit_group;" ::: "memory");
            asm volatile("cp.async.wait_group 1;" ::: "memory");
        } else {
            asm volatile("cp.async.wait_group 0;" ::: "memory");
        }
        __syncthreads();

        const float* Kt = Ks + st * TILE_KEYS * DK;
        const float* Vt = Vs + st * TILE_KEYS * DV;
        const int jt0 = jq + t * TILE_KEYS;

#pragma unroll 2
        for (int s = 0; s < 8; s++) {
            float4 d4[2], k4[2], v4[2];
            float  sc[2];
#pragma unroll
            for (int u = 0; u < 2; u++) {
                const int kk = h2 * 32 + s * 4 + 2 * u + h;  // in-tile key
                d4[u] = *(const float4*)&Drow[(size_t)(jt0 + kk) * DR + 4 * lx];
                k4[u] = *(const float4*)&Kt[kk * DK + 4 * lx];
                v4[u] = *(const float4*)&Vt[kk * DV + 4 * lx];
            }
#pragma unroll
            for (int u = 0; u < 2; u++) {
                float t0 = d4[u].x * r4.x;
                t0 = fmaf(d4[u].y, r4.y, t0);
                t0 = fmaf(d4[u].z, r4.z, t0);
                t0 = fmaf(d4[u].w, r4.w, t0);
                t0 = fmaf(k4[u].x, q4.x, t0);
                t0 = fmaf(k4[u].y, q4.y, t0);
                t0 = fmaf(k4[u].z, q4.z, t0);
                t0 = fmaf(k4[u].w, q4.w, t0);
                sc[u] = t0;
            }
#pragma unroll
            for (int o = 1; o < 16; o <<= 1) {
                sc[0] += __shfl_xor_sync(0xffffffffu, sc[0], o);
                sc[1] += __shfl_xor_sync(0xffffffffu, sc[1], o);
            }
            const float mnew = fmaxf(m, fmaxf(sc[0], sc[1]));
            const float c  = __expf(m - mnew);
            const float w0 = __expf(sc[0] - mnew);
            const float w1 = __expf(sc[1] - mnew);
            l = fmaf(l, c, w0 + w1);
            acc.x = fmaf(w1, v4[1].x, fmaf(w0, v4[0].x, acc.x * c));
            acc.y = fmaf(w1, v4[1].y, fmaf(w0, v4[0].y, acc.y * c));
            acc.z = fmaf(w1, v4[1].z, fmaf(w0, v4[0].z, acc.z * c));
            acc.w = fmaf(w1, v4[1].w, fmaf(w0, v4[0].w, acc.w * c));
            m = mnew;
        }
        __syncthreads();   // tile consumed; its buffer may be overwritten next iter
    }

    // ---- combine the 4 partials per row (2 warps x 2 groups) ----
    const int p = h2 * 2 + h;
    if (lx == 0) { cm[rloc * 4 + p] = m; cl[rloc * 4 + p] = l; }
    *(float4*)&ca[(rloc * 4 + p) * DV + 4 * lx] = acc;
    __syncthreads();

    {
        const int row = tid >> 6;           // 0..3
        const int d   = tid & 63;
        const int ig  = blockIdx.x * G_ROWS + row;
        float M = cm[row * 4 + 0];
#pragma unroll
        for (int w = 1; w < 4; w++) M = fmaxf(M, cm[row * 4 + w]);
        float L = 0.f, o = 0.f;
#pragma unroll
        for (int w = 0; w < 4; w++) {
            const float e = __expf(cm[row * 4 + w] - M);
            L = fmaf(cl[row * 4 + w], e, L);
            o = fmaf(ca[(row * 4 + w) * DV + d], e, o);
        }
        g_pa[q][ig][d] = o;
        if (d == 0) { g_ml[q][ig][0] = M; g_ml[q][ig][1] = L; }
    }
}

// ---------------------------------------------------------------------------
// Kernel 3: combine the two key-half partials per row.
// ---------------------------------------------------------------------------
__global__ __launch_bounds__(256) void combine_kernel(float* __restrict__ out)
{
    const int idx = blockIdx.x * 256 + threadIdx.x;   // 0 .. 2048*64-1
    const int i = idx >> 6;
    const int d = idx & 63;
    const float m0 = g_ml[0][i][0], l0 = g_ml[0][i][1];
    const float m1 = g_ml[1][i][0], l1 = g_ml[1][i][1];
    const float M  = fmaxf(m0, m1);
    const float e0 = __expf(m0 - M);
    const float e1 = __expf(m1 - M);
    const float L  = e0 * l0 + e1 * l1;
    out[idx] = (e0 * g_pa[0][i][d] + e1 * g_pa[1][i][d]) / L;
}

// ---------------------------------------------------------------------------
extern "C" void kernel_launch(void* const* d_in, const int* in_sizes, int n_in,
                              void* d_out, int out_size)
{
    const float* H = (const float*)d_in[0];   // (2048, 256)
    const float* D = (const float*)d_in[1];   // (2048, 2048, 64)
    const float* W = (const float*)d_in[2];   // (256, 256)
    float* out = (float*)d_out;               // (2048, 64)

    static bool attr_set = false;
    if (!attr_set) {
        cudaFuncSetAttribute(attn_partial_kernel,
                             cudaFuncAttributeMaxDynamicSharedMemorySize, SMEM_BYTES);
        attr_set = true;
    }

    dim3 g1(DPROJ / 64, NROWS / 64);
    proj_gemm_kernel<<<g1, 256>>>(H, W);
    attn_partial_kernel<<<dim3(NCTA_X, 2), 256, SMEM_BYTES>>>(D);
    combine_kernel<<<(NROWS * DV) / 256, 256>>>(out);
}

// round 7
// speedup vs baseline: 1.6795x; 1.1890x over previous
#include <cuda_runtime.h>
#include <math_constants.h>
#include <cstdint>

#define NROWS 2048
#define DIN   256
#define DPROJ 256   // Q[0:64) K[64:128) V[128:192) R[192:256)
#define DK    64
#define DR    64
#define DV    64

#define G_ROWS     4            // rows per CTA
#define TILE_KEYS  32           // keys per smem K/V tile
#define HALF_KEYS  1024         // keys per CTA (row split in 2)
#define NT         (HALF_KEYS / TILE_KEYS)   // 32 tiles
#define NCTA_X     (NROWS / G_ROWS)          // 512
// dynamic smem: Ks[2][32][64] + Vs[2][32][64] + cm[16] + cl[16] + ca[4][4][64]
#define SMEM_FLOATS (2*TILE_KEYS*DK + 2*TILE_KEYS*DV + 16 + 16 + G_ROWS*4*DV)
#define SMEM_BYTES  (SMEM_FLOATS * 4)

// Scratch
__device__ float g_proj[NROWS * DPROJ];          // projection (2 MB)
__device__ float g_ml[2][NROWS][2];              // per-half (M, L)
__device__ float g_pa[2][NROWS][DV];             // per-half unnormalized acc

__device__ __forceinline__ uint32_t smem_u32(const void* p) {
    return (uint32_t)__cvta_generic_to_shared(p);
}
__device__ __forceinline__ void cp16(uint32_t dst, const void* src) {
    asm volatile("cp.async.cg.shared.global [%0], [%1], 16;"
                 :: "r"(dst), "l"(src) : "memory");
}
// L2 evict-first policy (single-use stream) for 128-bit loads: must use the
// cache_hint form on sm_103 (direct .L2::evict_first only exists for 256-bit).
__device__ __forceinline__ uint64_t mk_evict_first_policy() {
    uint64_t pol;
    asm("createpolicy.fractional.L2::evict_first.b64 %0, 1.0;" : "=l"(pol));
    return pol;
}
__device__ __forceinline__ float4 ldg_stream(const float* p, uint64_t pol) {
    float4 v;
    asm volatile("ld.global.nc.L2::cache_hint.v4.f32 {%0,%1,%2,%3}, [%4], %5;"
                 : "=f"(v.x), "=f"(v.y), "=f"(v.z), "=f"(v.w)
                 : "l"(p), "l"(pol));
    return v;
}

// ---------------------------------------------------------------------------
// Kernel 1: proj = H @ W^T.  BM=32 -> 256 blocks (>148 SMs).
// ---------------------------------------------------------------------------
__global__ __launch_bounds__(256) void proj_gemm_kernel(
    const float* __restrict__ H, const float* __restrict__ W)
{
    const int BM = 32, BN = 64, BK = 32;
    __shared__ float As[BM][BK + 1];
    __shared__ float Bs[BN][BK + 1];

    const int tid = threadIdx.x;
    const int tx  = tid & 15;        // cols of 4
    const int ty  = tid >> 4;        // rows of 2
    const int bm  = blockIdx.y * BM;
    const int bn  = blockIdx.x * BN;

    float acc[2][4];
#pragma unroll
    for (int a = 0; a < 2; a++)
#pragma unroll
        for (int b = 0; b < 4; b++) acc[a][b] = 0.f;

    const int ar = tid >> 3;            // 0..31
    const int ac = (tid & 7) * 4;       // 0..28
    const int br = tid >> 2;            // 0..63
    const int bc = (tid & 3) * 8;       // 0,8,16,24

    for (int k0 = 0; k0 < DIN; k0 += BK) {
        {
            float4 a4 = *(const float4*)&H[(size_t)(bm + ar) * DIN + k0 + ac];
            As[ar][ac + 0] = a4.x; As[ar][ac + 1] = a4.y;
            As[ar][ac + 2] = a4.z; As[ar][ac + 3] = a4.w;
        }
#pragma unroll
        for (int h = 0; h < 2; h++) {
            float4 b4 = *(const float4*)&W[(size_t)(bn + br) * DIN + k0 + bc + 4 * h];
            Bs[br][bc + 4 * h + 0] = b4.x; Bs[br][bc + 4 * h + 1] = b4.y;
            Bs[br][bc + 4 * h + 2] = b4.z; Bs[br][bc + 4 * h + 3] = b4.w;
        }
        __syncthreads();
#pragma unroll
        for (int k = 0; k < BK; k++) {
            float af[2], bf[4];
#pragma unroll
            for (int a = 0; a < 2; a++) af[a] = As[ty * 2 + a][k];
#pragma unroll
            for (int b = 0; b < 4; b++) bf[b] = Bs[tx * 4 + b][k];
#pragma unroll
            for (int a = 0; a < 2; a++)
#pragma unroll
                for (int b = 0; b < 4; b++) acc[a][b] = fmaf(af[a], bf[b], acc[a][b]);
        }
        __syncthreads();
    }
#pragma unroll
    for (int a = 0; a < 2; a++)
#pragma unroll
        for (int b = 0; b < 4; b++)
            g_proj[(size_t)(bm + ty * 2 + a) * DPROJ + bn + tx * 4 + b] = acc[a][b];
}

// ---------------------------------------------------------------------------
// Kernel 2: partial fused attention.
// Grid (512, 2): blockIdx.x -> 4-row group, blockIdx.y = key half.
// 8 warps: warp w -> row rloc = w>>1, key-subset h2 = w&1 (16 keys/tile/warp).
// K/V double-buffered in smem (cp.async.cg), shared by 4 rows.
// D: 4 back-to-back LDG.128 (2KB) per 8-key batch, nc + L2 evict-first hint.
// ---------------------------------------------------------------------------
__global__ void __launch_bounds__(256, 4) attn_partial_kernel(
    const float* __restrict__ D)
{
    extern __shared__ float smem[];
    float* Ks = smem;                       // [2][TILE_KEYS][DK]
    float* Vs = Ks + 2 * TILE_KEYS * DK;    // [2][TILE_KEYS][DV]
    float* cm = Vs + 2 * TILE_KEYS * DV;    // [G_ROWS][4]
    float* cl = cm + 16;                    // [G_ROWS][4]
    float* ca = cl + 16;                    // [G_ROWS][4][DV]

    const int tid  = threadIdx.x;
    const int warp = tid >> 5;
    const int lane = tid & 31;
    const int h    = lane >> 4;          // group in warp
    const int lx   = lane & 15;          // lane in group -> dims 4*lx..+4
    const int rloc = warp >> 1;          // row within CTA
    const int h2   = warp & 1;           // key subset within tile
    const int q    = blockIdx.y;         // key half
    const int i    = blockIdx.x * G_ROWS + rloc;
    const int jq   = q * HALF_KEYS;

    const uint64_t pol = mk_evict_first_policy();

    const float scale = 0.08838834764831845f;  // 1/sqrt(128)
    float4 q4 = *(const float4*)&g_proj[(size_t)i * DPROJ + 4 * lx];
    float4 r4 = *(const float4*)&g_proj[(size_t)i * DPROJ + 192 + 4 * lx];
    q4.x *= scale; q4.y *= scale; q4.z *= scale; q4.w *= scale;
    r4.x *= scale; r4.y *= scale; r4.z *= scale; r4.w *= scale;

    const float* Drow = D + (size_t)i * NROWS * DR;

    // ---- prefetch tile 0 (K+V: 32 keys x 256B each = 16 KB) ----
    {
#pragma unroll
        for (int r = 0; r < 2; r++) {
            const int c   = tid + r * 256;      // 0..511
            const int key = c >> 4;
            const int off = c & 15;             // 16B units
            const float* src = &g_proj[(size_t)(jq + key) * DPROJ + off * 4];
            cp16(smem_u32(&Ks[key * DK + off * 4]), src + DK);
            cp16(smem_u32(&Vs[key * DV + off * 4]), src + 2 * DK);
        }
        asm volatile("cp.async.commit_group;" ::: "memory");
    }

    float  m = -CUDART_INF_F;
    float  l = 0.f;
    float4 acc = make_float4(0.f, 0.f, 0.f, 0.f);

#pragma unroll 1
    for (int t = 0; t < NT; t++) {
        const int st = t & 1;
        if (t + 1 < NT) {
            const int jt = jq + (t + 1) * TILE_KEYS;
            const int sn = (t + 1) & 1;
#pragma unroll
            for (int r = 0; r < 2; r++) {
                const int c   = tid + r * 256;
                const int key = c >> 4;
                const int off = c & 15;
                const float* src = &g_proj[(size_t)(jt + key) * DPROJ + off * 4];
                cp16(smem_u32(&Ks[sn * TILE_KEYS * DK + key * DK + off * 4]), src + DK);
                cp16(smem_u32(&Vs[sn * TILE_KEYS * DV + key * DV + off * 4]), src + 2 * DK);
            }
            asm volatile("cp.async.commit_group;" ::: "memory");
            asm volatile("cp.async.wait_group 1;" ::: "memory");
        } else {
            asm volatile("cp.async.wait_group 0;" ::: "memory");
        }
        __syncthreads();

        const float* Kt = Ks + st * TILE_KEYS * DK;
        const float* Vt = Vs + st * TILE_KEYS * DV;
        const int jt0 = jq + t * TILE_KEYS;
        const int kbase = h2 * 16;          // this warp's 16 keys in the tile

#pragma unroll
        for (int s = 0; s < 2; s++) {
            // ---- 8 keys per batch: 4 back-to-back 2KB-contiguous D loads ----
            float4 d4[4];
            float  sc[4];
#pragma unroll
            for (int u = 0; u < 4; u++) {
                const int kk = kbase + s * 8 + 2 * u + h;
                d4[u] = ldg_stream(&Drow[(size_t)(jt0 + kk) * DR + 4 * lx], pol);
            }
#pragma unroll
            for (int u = 0; u < 4; u++) {
                const int kk = kbase + s * 8 + 2 * u + h;
                const float4 k4 = *(const float4*)&Kt[kk * DK + 4 * lx];
                float t0 = d4[u].x * r4.x;
                t0 = fmaf(d4[u].y, r4.y, t0);
                t0 = fmaf(d4[u].z, r4.z, t0);
                t0 = fmaf(d4[u].w, r4.w, t0);
                t0 = fmaf(k4.x, q4.x, t0);
                t0 = fmaf(k4.y, q4.y, t0);
                t0 = fmaf(k4.z, q4.z, t0);
                t0 = fmaf(k4.w, q4.w, t0);
                sc[u] = t0;
            }
#pragma unroll
            for (int o = 1; o < 16; o <<= 1) {
#pragma unroll
                for (int u = 0; u < 4; u++)
                    sc[u] += __shfl_xor_sync(0xffffffffu, sc[u], o);
            }
            const float mnew = fmaxf(fmaxf(fmaxf(sc[0], sc[1]), fmaxf(sc[2], sc[3])), m);
            const float c = __expf(m - mnew);
            float w[4];
#pragma unroll
            for (int u = 0; u < 4; u++) w[u] = __expf(sc[u] - mnew);
            l = fmaf(l, c, (w[0] + w[1]) + (w[2] + w[3]));
            float ax = acc.x * c, ay = acc.y * c, az = acc.z * c, aw = acc.w * c;
#pragma unroll
            for (int u = 0; u < 4; u++) {
                const int kk = kbase + s * 8 + 2 * u + h;
                const float4 v4 = *(const float4*)&Vt[kk * DV + 4 * lx];
                ax = fmaf(w[u], v4.x, ax);
                ay = fmaf(w[u], v4.y, ay);
                az = fmaf(w[u], v4.z, az);
                aw = fmaf(w[u], v4.w, aw);
            }
            acc.x = ax; acc.y = ay; acc.z = az; acc.w = aw;
            m = mnew;
        }
        __syncthreads();   // tile consumed
    }

    // ---- combine the 4 partials per row (2 warps x 2 groups) ----
    const int p = h2 * 2 + h;
    if (lx == 0) { cm[rloc * 4 + p] = m; cl[rloc * 4 + p] = l; }
    *(float4*)&ca[(rloc * 4 + p) * DV + 4 * lx] = acc;
    __syncthreads();

    {
        const int row = tid >> 6;           // 0..3
        const int d   = tid & 63;
        const int ig  = blockIdx.x * G_ROWS + row;
        float M = cm[row * 4 + 0];
#pragma unroll
        for (int w = 1; w < 4; w++) M = fmaxf(M, cm[row * 4 + w]);
        float L = 0.f, o = 0.f;
#pragma unroll
        for (int w = 0; w < 4; w++) {
            const float e = __expf(cm[row * 4 + w] - M);
            L = fmaf(cl[row * 4 + w], e, L);
            o = fmaf(ca[(row * 4 + w) * DV + d], e, o);
        }
        g_pa[q][ig][d] = o;
        if (d == 0) { g_ml[q][ig][0] = M; g_ml[q][ig][1] = L; }
    }
}

// ---------------------------------------------------------------------------
// Kernel 3: combine the two key-half partials per row.
// ---------------------------------------------------------------------------
__global__ __launch_bounds__(256) void combine_kernel(float* __restrict__ out)
{
    const int idx = blockIdx.x * 256 + threadIdx.x;   // 0 .. 2048*64-1
    const int i = idx >> 6;
    const int d = idx & 63;
    const float m0 = g_ml[0][i][0], l0 = g_ml[0][i][1];
    const float m1 = g_ml[1][i][0], l1 = g_ml[1][i][1];
    const float M  = fmaxf(m0, m1);
    const float e0 = __expf(m0 - M);
    const float e1 = __expf(m1 - M);
    const float L  = e0 * l0 + e1 * l1;
    out[idx] = (e0 * g_pa[0][i][d] + e1 * g_pa[1][i][d]) / L;
}

// ---------------------------------------------------------------------------
extern "C" void kernel_launch(void* const* d_in, const int* in_sizes, int n_in,
                              void* d_out, int out_size)
{
    const float* H = (const float*)d_in[0];   // (2048, 256)
    const float* D = (const float*)d_in[1];   // (2048, 2048, 64)
    const float* W = (const float*)d_in[2];   // (256, 256)
    float* out = (float*)d_out;               // (2048, 64)

    static bool attr_set = false;
    if (!attr_set) {
        cudaFuncSetAttribute(attn_partial_kernel,
                             cudaFuncAttributeMaxDynamicSharedMemorySize, SMEM_BYTES);
        attr_set = true;
    }

    dim3 g1(DPROJ / 64, NROWS / 32);          // (4, 64) = 256 blocks
    proj_gemm_kernel<<<g1, 256>>>(H, W);
    attn_partial_kernel<<<dim3(NCTA_X, 2), 256, SMEM_BYTES>>>(D);
    combine_kernel<<<(NROWS * DV) / 256, 256>>>(out);
}

// round 8
// speedup vs baseline: 1.7885x; 1.0649x over previous
#include <cuda_runtime.h>
#include <math_constants.h>
#include <cstdint>

#define NROWS 2048
#define DIN   256
#define DPROJ 256   // Q[0:64) K[64:128) V[128:192) R[192:256)
#define DK    64
#define DR    64
#define DV    64

#define G_ROWS     8            // rows per CTA (one warp per row)
#define TILE_KEYS  32           // keys per smem K/V tile
#define HALF_KEYS  1024         // keys per CTA (row split in 2)
#define NT         (HALF_KEYS / TILE_KEYS)   // 32 tiles
#define NCTA_X     (NROWS / G_ROWS)          // 256
// dynamic smem: Ks[2][32][64] + Vs[2][32][64] + cm[16] + cl[16] + ca[8][2][64]
#define SMEM_FLOATS (2*TILE_KEYS*DK + 2*TILE_KEYS*DV + 16 + 16 + G_ROWS*2*DV)
#define SMEM_BYTES  (SMEM_FLOATS * 4)

// proj kernel smem: As[256][34] + Bs[256][68]
#define PAD_A 34
#define PAD_B 68
#define PROJ_SMEM_BYTES ((DIN * PAD_A + DIN * PAD_B) * 4)   // 104448

// Scratch
__device__ float g_proj[NROWS * DPROJ];          // projection (2 MB)
__device__ float g_ml[2][NROWS][2];              // per-half (M, L)
__device__ float g_pa[2][NROWS][DV];             // per-half unnormalized acc

__device__ __forceinline__ uint32_t smem_u32(const void* p) {
    return (uint32_t)__cvta_generic_to_shared(p);
}
__device__ __forceinline__ void cp16(uint32_t dst, const void* src) {
    asm volatile("cp.async.cg.shared.global [%0], [%1], 16;"
                 :: "r"(dst), "l"(src) : "memory");
}
__device__ __forceinline__ uint64_t mk_evict_first_policy() {
    uint64_t pol;
    asm("createpolicy.fractional.L2::evict_first.b64 %0, 1.0;" : "=l"(pol));
    return pol;
}
__device__ __forceinline__ float4 ldg_stream(const float* p, uint64_t pol) {
    float4 v;
    asm volatile("ld.global.nc.L2::cache_hint.v4.f32 {%0,%1,%2,%3}, [%4], %5;"
                 : "=f"(v.x), "=f"(v.y), "=f"(v.z), "=f"(v.w)
                 : "l"(p), "l"(pol));
    return v;
}

// ---------------------------------------------------------------------------
// Kernel 1: proj = H @ W^T.  Load-all-then-compute: both tiles staged k-major
// in smem with one barrier, then 256 pure-FMA k-steps (broadcast LDS).
// BM=32, BN=64, 256 threads, grid (4, 64) = 256 CTAs, 2 CTAs/SM.
// ---------------------------------------------------------------------------
__global__ __launch_bounds__(256, 2) void proj_gemm_kernel(
    const float* __restrict__ H, const float* __restrict__ W)
{
    extern __shared__ float psm[];
    float* As = psm;                   // [DIN][PAD_A]  (k-major, 32 rows used)
    float* Bs = psm + DIN * PAD_A;     // [DIN][PAD_B]  (k-major, 64 rows used)

    const int tid = threadIdx.x;
    const int bm  = blockIdx.y * 32;
    const int bn  = blockIdx.x * 64;

    // ---- stage H tile (32 x 256) transposed ----
    {
        const int row = tid >> 3;           // 0..31
        const int c   = (tid & 7) * 4;      // k sub-offset
#pragma unroll
        for (int kc = 0; kc < DIN; kc += 32) {
            float4 a4 = *(const float4*)&H[(size_t)(bm + row) * DIN + kc + c];
            As[(kc + c + 0) * PAD_A + row] = a4.x;
            As[(kc + c + 1) * PAD_A + row] = a4.y;
            As[(kc + c + 2) * PAD_A + row] = a4.z;
            As[(kc + c + 3) * PAD_A + row] = a4.w;
        }
    }
    // ---- stage W tile (64 x 256) transposed ----
    {
        const int row = tid >> 2;           // 0..63
        const int c   = (tid & 3) * 4;
#pragma unroll
        for (int kc = 0; kc < DIN; kc += 16) {
            float4 b4 = *(const float4*)&W[(size_t)(bn + row) * DIN + kc + c];
            Bs[(kc + c + 0) * PAD_B + row] = b4.x;
            Bs[(kc + c + 1) * PAD_B + row] = b4.y;
            Bs[(kc + c + 2) * PAD_B + row] = b4.z;
            Bs[(kc + c + 3) * PAD_B + row] = b4.w;
        }
    }
    __syncthreads();   // the only barrier

    const int tx = tid & 15;        // 4 output cols
    const int ty = tid >> 4;        // 2 output rows

    float acc[2][4];
#pragma unroll
    for (int a = 0; a < 2; a++)
#pragma unroll
        for (int b = 0; b < 4; b++) acc[a][b] = 0.f;

#pragma unroll 4
    for (int k = 0; k < DIN; k++) {
        const float2 af = *(const float2*)&As[k * PAD_A + ty * 2];
        const float4 bf = *(const float4*)&Bs[k * PAD_B + tx * 4];
        acc[0][0] = fmaf(af.x, bf.x, acc[0][0]);
        acc[0][1] = fmaf(af.x, bf.y, acc[0][1]);
        acc[0][2] = fmaf(af.x, bf.z, acc[0][2]);
        acc[0][3] = fmaf(af.x, bf.w, acc[0][3]);
        acc[1][0] = fmaf(af.y, bf.x, acc[1][0]);
        acc[1][1] = fmaf(af.y, bf.y, acc[1][1]);
        acc[1][2] = fmaf(af.y, bf.z, acc[1][2]);
        acc[1][3] = fmaf(af.y, bf.w, acc[1][3]);
    }

#pragma unroll
    for (int a = 0; a < 2; a++)
        *(float4*)&g_proj[(size_t)(bm + ty * 2 + a) * DPROJ + bn + tx * 4] =
            make_float4(acc[a][0], acc[a][1], acc[a][2], acc[a][3]);
}

// ---------------------------------------------------------------------------
// Kernel 2: partial fused attention.
// Grid (256, 2): blockIdx.x -> 8-row group, blockIdx.y = key half.
// 8 warps: warp w owns row w; it processes the full 32-key tile in 4 batches
// of 8 keys (16-lane groups h own alternating keys, lane&15 owns 4 dims).
// K/V double-buffered in smem (cp.async.cg), shared by the 8 rows.
// D: 4 back-to-back LDG.128 per 8-key batch (8KB/warp/tile), evict-first.
// ---------------------------------------------------------------------------
__global__ void __launch_bounds__(256, 4) attn_partial_kernel(
    const float* __restrict__ D)
{
    extern __shared__ float smem[];
    float* Ks = smem;                       // [2][TILE_KEYS][DK]
    float* Vs = Ks + 2 * TILE_KEYS * DK;    // [2][TILE_KEYS][DV]
    float* cm = Vs + 2 * TILE_KEYS * DV;    // [G_ROWS][2]
    float* cl = cm + 16;                    // [G_ROWS][2]
    float* ca = cl + 16;                    // [G_ROWS][2][DV]

    const int tid  = threadIdx.x;
    const int warp = tid >> 5;           // = row within CTA
    const int lane = tid & 31;
    const int h    = lane >> 4;          // group in warp
    const int lx   = lane & 15;          // lane in group -> dims 4*lx..+4
    const int q    = blockIdx.y;         // key half
    const int i    = blockIdx.x * G_ROWS + warp;
    const int jq   = q * HALF_KEYS;

    const uint64_t pol = mk_evict_first_policy();

    const float scale = 0.08838834764831845f;  // 1/sqrt(128)
    float4 q4 = *(const float4*)&g_proj[(size_t)i * DPROJ + 4 * lx];
    float4 r4 = *(const float4*)&g_proj[(size_t)i * DPROJ + 192 + 4 * lx];
    q4.x *= scale; q4.y *= scale; q4.z *= scale; q4.w *= scale;
    r4.x *= scale; r4.y *= scale; r4.z *= scale; r4.w *= scale;

    const float* Drow = D + (size_t)i * NROWS * DR;

    // ---- prefetch tile 0 (K+V: 32 keys x 256B each = 16 KB) ----
    {
#pragma unroll
        for (int r = 0; r < 2; r++) {
            const int c   = tid + r * 256;      // 0..511
            const int key = c >> 4;
            const int off = c & 15;             // 16B units
            const float* src = &g_proj[(size_t)(jq + key) * DPROJ + off * 4];
            cp16(smem_u32(&Ks[key * DK + off * 4]), src + DK);
            cp16(smem_u32(&Vs[key * DV + off * 4]), src + 2 * DK);
        }
        asm volatile("cp.async.commit_group;" ::: "memory");
    }

    float  m = -CUDART_INF_F;
    float  l = 0.f;
    float4 acc = make_float4(0.f, 0.f, 0.f, 0.f);

#pragma unroll 1
    for (int t = 0; t < NT; t++) {
        const int st = t & 1;
        if (t + 1 < NT) {
            const int jt = jq + (t + 1) * TILE_KEYS;
            const int sn = (t + 1) & 1;
#pragma unroll
            for (int r = 0; r < 2; r++) {
                const int c   = tid + r * 256;
                const int key = c >> 4;
                const int off = c & 15;
                const float* src = &g_proj[(size_t)(jt + key) * DPROJ + off * 4];
                cp16(smem_u32(&Ks[sn * TILE_KEYS * DK + key * DK + off * 4]), src + DK);
                cp16(smem_u32(&Vs[sn * TILE_KEYS * DV + key * DV + off * 4]), src + 2 * DK);
            }
            asm volatile("cp.async.commit_group;" ::: "memory");
            asm volatile("cp.async.wait_group 1;" ::: "memory");
        } else {
            asm volatile("cp.async.wait_group 0;" ::: "memory");
        }
        __syncthreads();

        const float* Kt = Ks + st * TILE_KEYS * DK;
        const float* Vt = Vs + st * TILE_KEYS * DV;
        const int jt0 = jq + t * TILE_KEYS;

#pragma unroll
        for (int s = 0; s < 4; s++) {
            // ---- 8 keys per batch: 4 back-to-back 2KB-contiguous D loads ----
            float4 d4[4];
            float  sc[4];
#pragma unroll
            for (int u = 0; u < 4; u++) {
                const int kk = s * 8 + 2 * u + h;
                d4[u] = ldg_stream(&Drow[(size_t)(jt0 + kk) * DR + 4 * lx], pol);
            }
#pragma unroll
            for (int u = 0; u < 4; u++) {
                const int kk = s * 8 + 2 * u + h;
                const float4 k4 = *(const float4*)&Kt[kk * DK + 4 * lx];
                float t0 = d4[u].x * r4.x;
                t0 = fmaf(d4[u].y, r4.y, t0);
                t0 = fmaf(d4[u].z, r4.z, t0);
                t0 = fmaf(d4[u].w, r4.w, t0);
                t0 = fmaf(k4.x, q4.x, t0);
                t0 = fmaf(k4.y, q4.y, t0);
                t0 = fmaf(k4.z, q4.z, t0);
                t0 = fmaf(k4.w, q4.w, t0);
                sc[u] = t0;
            }
#pragma unroll
            for (int o = 1; o < 16; o <<= 1) {
#pragma unroll
                for (int u = 0; u < 4; u++)
                    sc[u] += __shfl_xor_sync(0xffffffffu, sc[u], o);
            }
            const float mnew = fmaxf(fmaxf(fmaxf(sc[0], sc[1]), fmaxf(sc[2], sc[3])), m);
            const float c = __expf(m - mnew);
            float w[4];
#pragma unroll
            for (int u = 0; u < 4; u++) w[u] = __expf(sc[u] - mnew);
            l = fmaf(l, c, (w[0] + w[1]) + (w[2] + w[3]));
            float ax = acc.x * c, ay = acc.y * c, az = acc.z * c, aw = acc.w * c;
#pragma unroll
            for (int u = 0; u < 4; u++) {
                const int kk = s * 8 + 2 * u + h;
                const float4 v4 = *(const float4*)&Vt[kk * DV + 4 * lx];
                ax = fmaf(w[u], v4.x, ax);
                ay = fmaf(w[u], v4.y, ay);
                az = fmaf(w[u], v4.z, az);
                aw = fmaf(w[u], v4.w, aw);
            }
            acc.x = ax; acc.y = ay; acc.z = az; acc.w = aw;
            m = mnew;
        }
        __syncthreads();   // tile consumed
    }

    // ---- combine the 2 group-partials per row ----
    if (lx == 0) { cm[warp * 2 + h] = m; cl[warp * 2 + h] = l; }
    *(float4*)&ca[(warp * 2 + h) * DV + 4 * lx] = acc;
    __syncthreads();

    {
        const int row = tid >> 5;           // 0..7
        const int dd  = (tid & 31) * 2;     // 2 dims per thread
        const int ig  = blockIdx.x * G_ROWS + row;
        const float m0 = cm[row * 2 + 0], m1 = cm[row * 2 + 1];
        const float M  = fmaxf(m0, m1);
        const float e0 = __expf(m0 - M);
        const float e1 = __expf(m1 - M);
        const float L  = e0 * cl[row * 2 + 0] + e1 * cl[row * 2 + 1];
        const float o0 = e0 * ca[(row * 2 + 0) * DV + dd + 0]
                       + e1 * ca[(row * 2 + 1) * DV + dd + 0];
        const float o1 = e0 * ca[(row * 2 + 0) * DV + dd + 1]
                       + e1 * ca[(row * 2 + 1) * DV + dd + 1];
        g_pa[q][ig][dd + 0] = o0;
        g_pa[q][ig][dd + 1] = o1;
        if (dd == 0) { g_ml[q][ig][0] = M; g_ml[q][ig][1] = L; }
    }
}

// ---------------------------------------------------------------------------
// Kernel 3: combine the two key-half partials per row.
// ---------------------------------------------------------------------------
__global__ __launch_bounds__(256) void combine_kernel(float* __restrict__ out)
{
    const int idx = blockIdx.x * 256 + threadIdx.x;   // 0 .. 2048*64-1
    const int i = idx >> 6;
    const int d = idx & 63;
    const float m0 = g_ml[0][i][0], l0 = g_ml[0][i][1];
    const float m1 = g_ml[1][i][0], l1 = g_ml[1][i][1];
    const float M  = fmaxf(m0, m1);
    const float e0 = __expf(m0 - M);
    const float e1 = __expf(m1 - M);
    const float L  = e0 * l0 + e1 * l1;
    out[idx] = (e0 * g_pa[0][i][d] + e1 * g_pa[1][i][d]) / L;
}

// ---------------------------------------------------------------------------
extern "C" void kernel_launch(void* const* d_in, const int* in_sizes, int n_in,
                              void* d_out, int out_size)
{
    const float* H = (const float*)d_in[0];   // (2048, 256)
    const float* D = (const float*)d_in[1];   // (2048, 2048, 64)
    const float* W = (const float*)d_in[2];   // (256, 256)
    float* out = (float*)d_out;               // (2048, 64)

    static bool attr_set = false;
    if (!attr_set) {
        cudaFuncSetAttribute(attn_partial_kernel,
                             cudaFuncAttributeMaxDynamicSharedMemorySize, SMEM_BYTES);
        cudaFuncSetAttribute(proj_gemm_kernel,
                             cudaFuncAttributeMaxDynamicSharedMemorySize, PROJ_SMEM_BYTES);
        attr_set = true;
    }

    dim3 g1(DPROJ / 64, NROWS / 32);          // (4, 64) = 256 blocks
    proj_gemm_kernel<<<g1, 256, PROJ_SMEM_BYTES>>>(H, W);
    attn_partial_kernel<<<dim3(NCTA_X, 2), 256, SMEM_BYTES>>>(D);
    combine_kernel<<<(NROWS * DV) / 256, 256>>>(out);
}

// round 9
// speedup vs baseline: 1.8057x; 1.0096x over previous
#include <cuda_runtime.h>
#include <math_constants.h>
#include <cstdint>

#define NROWS 2048
#define DIN   256
#define DPROJ 256   // Q[0:64) K[64:128) V[128:192) R[192:256)
#define DK    64
#define DR    64
#define DV    64

#define G_ROWS     8            // rows per CTA (one warp per row)
#define TILE_KEYS  32           // keys per smem K/V tile
#define HALF_KEYS  1024         // keys per CTA (row split in 2)
#define NT         (HALF_KEYS / TILE_KEYS)   // 32 tiles
#define NCTA_X     (NROWS / G_ROWS)          // 256
// dynamic smem: Ks[2][32][64] + Vs[2][32][64] + cm[16] + cl[16] + ca[8][2][64]
#define SMEM_FLOATS (2*TILE_KEYS*DK + 2*TILE_KEYS*DV + 16 + 16 + G_ROWS*2*DV)
#define SMEM_BYTES  (SMEM_FLOATS * 4)

// proj kernel smem: As[256][68] + Bs[256][68] (k-major, 64 rows used each)
#define PPAD 68
#define PROJ_SMEM_BYTES (2 * DIN * PPAD * 4)   // 139264

// Scratch
__device__ float g_proj[NROWS * DPROJ];          // projection (2 MB)
__device__ float g_ml[2][NROWS][2];              // per-half (M, L)
__device__ float g_pa[2][NROWS][DV];             // per-half unnormalized acc

__device__ __forceinline__ uint32_t smem_u32(const void* p) {
    return (uint32_t)__cvta_generic_to_shared(p);
}
__device__ __forceinline__ void cp16(uint32_t dst, const void* src) {
    asm volatile("cp.async.cg.shared.global [%0], [%1], 16;"
                 :: "r"(dst), "l"(src) : "memory");
}
__device__ __forceinline__ uint64_t mk_evict_first_policy() {
    uint64_t pol;
    asm("createpolicy.fractional.L2::evict_first.b64 %0, 1.0;" : "=l"(pol));
    return pol;
}
__device__ __forceinline__ float4 ldg_stream(const float* p, uint64_t pol) {
    float4 v;
    asm volatile("ld.global.nc.L2::cache_hint.v4.f32 {%0,%1,%2,%3}, [%4], %5;"
                 : "=f"(v.x), "=f"(v.y), "=f"(v.z), "=f"(v.w)
                 : "l"(p), "l"(pol));
    return v;
}

// ---------------------------------------------------------------------------
// Kernel 1: proj = H @ W^T.  BM=BN=64, 256 threads, 4x4 micro-tile.
// Full-K k-major staging of both tiles (one barrier), then 256 k-steps of
// 2 LDS.128 + 16 FMA. Grid (4,32)=128 CTAs, 1 CTA/SM, single wave.
// ---------------------------------------------------------------------------
__global__ __launch_bounds__(256, 1) void proj_gemm_kernel(
    const float* __restrict__ H, const float* __restrict__ W)
{
    extern __shared__ float psm[];
    float* As = psm;                   // [DIN][PPAD] rows 0..63 used
    float* Bs = psm + DIN * PPAD;      // [DIN][PPAD] rows 0..63 used

    const int tid = threadIdx.x;
    const int bm  = blockIdx.y * 64;
    const int bn  = blockIdx.x * 64;

    // ---- stage H tile (64 x 256) and W tile (64 x 256), k-major ----
    {
        const int row = tid >> 2;           // 0..63
        const int c   = (tid & 3) * 4;      // k sub-offset
#pragma unroll
        for (int kc = 0; kc < DIN; kc += 16) {
            float4 a4 = *(const float4*)&H[(size_t)(bm + row) * DIN + kc + c];
            As[(kc + c + 0) * PPAD + row] = a4.x;
            As[(kc + c + 1) * PPAD + row] = a4.y;
            As[(kc + c + 2) * PPAD + row] = a4.z;
            As[(kc + c + 3) * PPAD + row] = a4.w;
            float4 b4 = *(const float4*)&W[(size_t)(bn + row) * DIN + kc + c];
            Bs[(kc + c + 0) * PPAD + row] = b4.x;
            Bs[(kc + c + 1) * PPAD + row] = b4.y;
            Bs[(kc + c + 2) * PPAD + row] = b4.z;
            Bs[(kc + c + 3) * PPAD + row] = b4.w;
        }
    }
    __syncthreads();   // the only barrier

    const int tx = tid & 15;        // 4 output cols
    const int ty = tid >> 4;        // 4 output rows

    float acc[4][4];
#pragma unroll
    for (int a = 0; a < 4; a++)
#pragma unroll
        for (int b = 0; b < 4; b++) acc[a][b] = 0.f;

#pragma unroll 4
    for (int k = 0; k < DIN; k++) {
        const float4 af = *(const float4*)&As[k * PPAD + ty * 4];
        const float4 bf = *(const float4*)&Bs[k * PPAD + tx * 4];
        acc[0][0] = fmaf(af.x, bf.x, acc[0][0]);
        acc[0][1] = fmaf(af.x, bf.y, acc[0][1]);
        acc[0][2] = fmaf(af.x, bf.z, acc[0][2]);
        acc[0][3] = fmaf(af.x, bf.w, acc[0][3]);
        acc[1][0] = fmaf(af.y, bf.x, acc[1][0]);
        acc[1][1] = fmaf(af.y, bf.y, acc[1][1]);
        acc[1][2] = fmaf(af.y, bf.z, acc[1][2]);
        acc[1][3] = fmaf(af.y, bf.w, acc[1][3]);
        acc[2][0] = fmaf(af.z, bf.x, acc[2][0]);
        acc[2][1] = fmaf(af.z, bf.y, acc[2][1]);
        acc[2][2] = fmaf(af.z, bf.z, acc[2][2]);
        acc[2][3] = fmaf(af.z, bf.w, acc[2][3]);
        acc[3][0] = fmaf(af.w, bf.x, acc[3][0]);
        acc[3][1] = fmaf(af.w, bf.y, acc[3][1]);
        acc[3][2] = fmaf(af.w, bf.z, acc[3][2]);
        acc[3][3] = fmaf(af.w, bf.w, acc[3][3]);
    }

#pragma unroll
    for (int a = 0; a < 4; a++)
        *(float4*)&g_proj[(size_t)(bm + ty * 4 + a) * DPROJ + bn + tx * 4] =
            make_float4(acc[a][0], acc[a][1], acc[a][2], acc[a][3]);
}

// ---------------------------------------------------------------------------
// Kernel 2: partial fused attention.  (unchanged from R8)
// Grid (256, 2): blockIdx.x -> 8-row group, blockIdx.y = key half.
// 8 warps: warp w owns row w; 32-key K/V tiles double-buffered in smem,
// D streamed as 4 back-to-back LDG.128 per 8-key batch, evict-first.
// ---------------------------------------------------------------------------
__global__ void __launch_bounds__(256, 4) attn_partial_kernel(
    const float* __restrict__ D)
{
    extern __shared__ float smem[];
    float* Ks = smem;                       // [2][TILE_KEYS][DK]
    float* Vs = Ks + 2 * TILE_KEYS * DK;    // [2][TILE_KEYS][DV]
    float* cm = Vs + 2 * TILE_KEYS * DV;    // [G_ROWS][2]
    float* cl = cm + 16;                    // [G_ROWS][2]
    float* ca = cl + 16;                    // [G_ROWS][2][DV]

    const int tid  = threadIdx.x;
    const int warp = tid >> 5;           // = row within CTA
    const int lane = tid & 31;
    const int h    = lane >> 4;          // group in warp
    const int lx   = lane & 15;          // lane in group -> dims 4*lx..+4
    const int q    = blockIdx.y;         // key half
    const int i    = blockIdx.x * G_ROWS + warp;
    const int jq   = q * HALF_KEYS;

    const uint64_t pol = mk_evict_first_policy();

    const float scale = 0.08838834764831845f;  // 1/sqrt(128)
    float4 q4 = *(const float4*)&g_proj[(size_t)i * DPROJ + 4 * lx];
    float4 r4 = *(const float4*)&g_proj[(size_t)i * DPROJ + 192 + 4 * lx];
    q4.x *= scale; q4.y *= scale; q4.z *= scale; q4.w *= scale;
    r4.x *= scale; r4.y *= scale; r4.z *= scale; r4.w *= scale;

    const float* Drow = D + (size_t)i * NROWS * DR;

    // ---- prefetch tile 0 (K+V: 32 keys x 256B each = 16 KB) ----
    {
#pragma unroll
        for (int r = 0; r < 2; r++) {
            const int c   = tid + r * 256;      // 0..511
            const int key = c >> 4;
            const int off = c & 15;             // 16B units
            const float* src = &g_proj[(size_t)(jq + key) * DPROJ + off * 4];
            cp16(smem_u32(&Ks[key * DK + off * 4]), src + DK);
            cp16(smem_u32(&Vs[key * DV + off * 4]), src + 2 * DK);
        }
        asm volatile("cp.async.commit_group;" ::: "memory");
    }

    float  m = -CUDART_INF_F;
    float  l = 0.f;
    float4 acc = make_float4(0.f, 0.f, 0.f, 0.f);

#pragma unroll 1
    for (int t = 0; t < NT; t++) {
        const int st = t & 1;
        if (t + 1 < NT) {
            const int jt = jq + (t + 1) * TILE_KEYS;
            const int sn = (t + 1) & 1;
#pragma unroll
            for (int r = 0; r < 2; r++) {
                const int c   = tid + r * 256;
                const int key = c >> 4;
                const int off = c & 15;
                const float* src = &g_proj[(size_t)(jt + key) * DPROJ + off * 4];
                cp16(smem_u32(&Ks[sn * TILE_KEYS * DK + key * DK + off * 4]), src + DK);
                cp16(smem_u32(&Vs[sn * TILE_KEYS * DV + key * DV + off * 4]), src + 2 * DK);
            }
            asm volatile("cp.async.commit_group;" ::: "memory");
            asm volatile("cp.async.wait_group 1;" ::: "memory");
        } else {
            asm volatile("cp.async.wait_group 0;" ::: "memory");
        }
        __syncthreads();

        const float* Kt = Ks + st * TILE_KEYS * DK;
        const float* Vt = Vs + st * TILE_KEYS * DV;
        const int jt0 = jq + t * TILE_KEYS;

#pragma unroll
        for (int s = 0; s < 4; s++) {
            // ---- 8 keys per batch: 4 back-to-back 2KB-contiguous D loads ----
            float4 d4[4];
            float  sc[4];
#pragma unroll
            for (int u = 0; u < 4; u++) {
                const int kk = s * 8 + 2 * u + h;
                d4[u] = ldg_stream(&Drow[(size_t)(jt0 + kk) * DR + 4 * lx], pol);
            }
#pragma unroll
            for (int u = 0; u < 4; u++) {
                const int kk = s * 8 + 2 * u + h;
                const float4 k4 = *(const float4*)&Kt[kk * DK + 4 * lx];
                float t0 = d4[u].x * r4.x;
                t0 = fmaf(d4[u].y, r4.y, t0);
                t0 = fmaf(d4[u].z, r4.z, t0);
                t0 = fmaf(d4[u].w, r4.w, t0);
                t0 = fmaf(k4.x, q4.x, t0);
                t0 = fmaf(k4.y, q4.y, t0);
                t0 = fmaf(k4.z, q4.z, t0);
                t0 = fmaf(k4.w, q4.w, t0);
                sc[u] = t0;
            }
#pragma unroll
            for (int o = 1; o < 16; o <<= 1) {
#pragma unroll
                for (int u = 0; u < 4; u++)
                    sc[u] += __shfl_xor_sync(0xffffffffu, sc[u], o);
            }
            const float mnew = fmaxf(fmaxf(fmaxf(sc[0], sc[1]), fmaxf(sc[2], sc[3])), m);
            const float c = __expf(m - mnew);
            float w[4];
#pragma unroll
            for (int u = 0; u < 4; u++) w[u] = __expf(sc[u] - mnew);
            l = fmaf(l, c, (w[0] + w[1]) + (w[2] + w[3]));
            float ax = acc.x * c, ay = acc.y * c, az = acc.z * c, aw = acc.w * c;
#pragma unroll
            for (int u = 0; u < 4; u++) {
                const int kk = s * 8 + 2 * u + h;
                const float4 v4 = *(const float4*)&Vt[kk * DV + 4 * lx];
                ax = fmaf(w[u], v4.x, ax);
                ay = fmaf(w[u], v4.y, ay);
                az = fmaf(w[u], v4.z, az);
                aw = fmaf(w[u], v4.w, aw);
            }
            acc.x = ax; acc.y = ay; acc.z = az; acc.w = aw;
            m = mnew;
        }
        __syncthreads();   // tile consumed
    }

    // ---- combine the 2 group-partials per row ----
    if (lx == 0) { cm[warp * 2 + h] = m; cl[warp * 2 + h] = l; }
    *(float4*)&ca[(warp * 2 + h) * DV + 4 * lx] = acc;
    __syncthreads();

    {
        const int row = tid >> 5;           // 0..7
        const int dd  = (tid & 31) * 2;     // 2 dims per thread
        const int ig  = blockIdx.x * G_ROWS + row;
        const float m0 = cm[row * 2 + 0], m1 = cm[row * 2 + 1];
        const float M  = fmaxf(m0, m1);
        const float e0 = __expf(m0 - M);
        const float e1 = __expf(m1 - M);
        const float L  = e0 * cl[row * 2 + 0] + e1 * cl[row * 2 + 1];
        const float o0 = e0 * ca[(row * 2 + 0) * DV + dd + 0]
                       + e1 * ca[(row * 2 + 1) * DV + dd + 0];
        const float o1 = e0 * ca[(row * 2 + 0) * DV + dd + 1]
                       + e1 * ca[(row * 2 + 1) * DV + dd + 1];
        g_pa[q][ig][dd + 0] = o0;
        g_pa[q][ig][dd + 1] = o1;
        if (dd == 0) { g_ml[q][ig][0] = M; g_ml[q][ig][1] = L; }
    }
}

// ---------------------------------------------------------------------------
// Kernel 3: combine the two key-half partials per row.
// ---------------------------------------------------------------------------
__global__ __launch_bounds__(256) void combine_kernel(float* __restrict__ out)
{
    const int idx = blockIdx.x * 256 + threadIdx.x;   // 0 .. 2048*64-1
    const int i = idx >> 6;
    const int d = idx & 63;
    const float m0 = g_ml[0][i][0], l0 = g_ml[0][i][1];
    const float m1 = g_ml[1][i][0], l1 = g_ml[1][i][1];
    const float M  = fmaxf(m0, m1);
    const float e0 = __expf(m0 - M);
    const float e1 = __expf(m1 - M);
    const float L  = e0 * l0 + e1 * l1;
    out[idx] = (e0 * g_pa[0][i][d] + e1 * g_pa[1][i][d]) / L;
}

// ---------------------------------------------------------------------------
extern "C" void kernel_launch(void* const* d_in, const int* in_sizes, int n_in,
                              void* d_out, int out_size)
{
    const float* H = (const float*)d_in[0];   // (2048, 256)
    const float* D = (const float*)d_in[1];   // (2048, 2048, 64)
    const float* W = (const float*)d_in[2];   // (256, 256)
    float* out = (float*)d_out;               // (2048, 64)

    static bool attr_set = false;
    if (!attr_set) {
        cudaFuncSetAttribute(attn_partial_kernel,
                             cudaFuncAttributeMaxDynamicSharedMemorySize, SMEM_BYTES);
        cudaFuncSetAttribute(proj_gemm_kernel,
                             cudaFuncAttributeMaxDynamicSharedMemorySize, PROJ_SMEM_BYTES);
        attr_set = true;
    }

    dim3 g1(DPROJ / 64, NROWS / 64);          // (4, 32) = 128 blocks
    proj_gemm_kernel<<<g1, 256, PROJ_SMEM_BYTES>>>(H, W);
    attn_partial_kernel<<<dim3(NCTA_X, 2), 256, SMEM_BYTES>>>(D);
    combine_kernel<<<(NROWS * DV) / 256, 256>>>(out);
}